// round 5
// baseline (speedup 1.0000x reference)
#include <cuda_runtime.h>
#include <cuda_bf16.h>

#define BCH   10
#define HH    320
#define WW    1024
#define PTS   500
#define DENSE 2000
#define KMEAN 10
#define NPTS  (BCH * PTS)
#define CHUNKS (DENSE / 4)      // 500 int4 chunks per point

#define GRID_BLOCKS 592         // 148 SMs * 4 CTAs/SM -> exactly one wave
#define TOTAL_WARPS (GRID_BLOCKS * 4)

__device__ int          g_bar;       // barrier arrival counter (self-resetting)
__device__ volatile int g_release;   // sense flag (toggles each replay)
__device__ int          g_count;     // compaction counter (reset by releaser)
__device__ int          g_count_ro;  // snapshot read by phase 2
__device__ int          g_queue[NPTS];

__global__ __launch_bounds__(128, 4)
void rsbsp_fused(const float* __restrict__ disp,
                 const float* __restrict__ fore,
                 const int*   __restrict__ cxs,
                 const int*   __restrict__ cys,
                 const int*   __restrict__ bxs,
                 const int*   __restrict__ bys,
                 float*       __restrict__ out)
{
    const int tid  = blockIdx.x * 128 + threadIdx.x;
    const int lane = threadIdx.x & 31;

    // ================= Phase 1: validity + output zeroing + compaction ======
    if (tid < NPTS) {
        const int n    = tid;
        out[2 * n]     = 0.0f;            // default; phase 2 overwrites valid rows
        out[2 * n + 1] = 0.0f;

        const int chan = n / PTS;
        const int cx   = cxs[n];
        const int cy   = cys[n];
        const float* dch = disp + (size_t)chan * (HH * WW);
        const float* fch = fore + (size_t)chan * (HH * WW);

        // maxpool3x3(|sobel_x(forepred)|)(cy,cx) from the 5x5 window.
        // Centers are >= 11 px from all borders -> no zeroArea/pad cases.
        float w[5][5];
        #pragma unroll
        for (int r = 0; r < 5; r++) {
            const float* p = fch + (size_t)(cy + r - 2) * WW + (cx - 2);
            #pragma unroll
            for (int c = 0; c < 5; c++) w[r][c] = p[c];
        }
        float best = 0.0f;
        #pragma unroll
        for (int r = 0; r < 3; r++) {
            #pragma unroll
            for (int c = 0; c < 3; c++) {
                const float a = w[r][c + 2] + 2.0f * w[r + 1][c + 2] + w[r + 2][c + 2];
                const float b = w[r][c]     + 2.0f * w[r + 1][c]     + w[r + 2][c];
                best = fmaxf(best, fabsf(a - b));
            }
        }
        const float dC = dch[(cy << 10) + cx];
        if ((best > 3.1f) && (dC > 0.007f)) {
            const int pos = atomicAdd(&g_count, 1);
            g_queue[pos] = n;
        }
    }

    // ================= Grid barrier (sense-reversal; one wave resident) =====
    __syncthreads();
    if (threadIdx.x == 0) {
        __threadfence();                       // queue/out writes visible
        const int sense = g_release;           // pre-flip by construction
        const int old   = atomicAdd(&g_bar, 1);
        if (old == GRID_BLOCKS - 1) {          // releaser: snapshot + reset
            g_bar      = 0;
            g_count_ro = g_count;
            g_count    = 0;                    // ready for next graph replay
            __threadfence();
            g_release  = sense ^ 1;
        } else {
            while (g_release == sense) { }     // all blocks resident -> safe
        }
    }
    __syncthreads();
    __threadfence();

    // ================= Phase 2: one warp per compacted valid point ==========
    const int count = g_count_ro;
    const int gwarp = (blockIdx.x * 128 + threadIdx.x) >> 5;

    for (int w = gwarp; w < count; w += TOTAL_WARPS) {
        const int n    = g_queue[w];
        const int chan = n / PTS;
        const int cx   = cxs[n];
        const int cy   = cys[n];
        const float* dch  = disp + (size_t)chan * (HH * WW);
        const int    base = (cy << 10) + cx;          // WW == 1024

        const int4* bx4p = (const int4*)(bxs + (size_t)n * DENSE);
        const int4* by4p = (const int4*)(bys + (size_t)n * DENSE);

        float sv[64];
        float mx = -1e30f, mn = 1e30f, stot = 0.0f;
        #pragma unroll
        for (int k = 0; k < 16; k++) {
            const int  c     = lane + (k << 5);
            const bool valid = (k < 15) || (c < CHUNKS);   // compile-time true k<15
            float v0 = -1e30f, v1 = -1e30f, v2 = -1e30f, v3 = -1e30f;  // pad
            if (valid) {
                const int4 b4 = bx4p[c];
                const int4 y4 = by4p[c];
                v0 = dch[base + y4.x * WW + b4.x];
                v1 = dch[base + y4.y * WW + b4.y];
                v2 = dch[base + y4.z * WW + b4.z];
                v3 = dch[base + y4.w * WW + b4.w];
                mx = fmaxf(fmaxf(mx, v0), fmaxf(v1, fmaxf(v2, v3)));
                mn = fminf(fminf(mn, v0), fminf(v1, fminf(v2, v3)));
                stot += (v0 + v1) + (v2 + v3);
            }
            sv[4 * k + 0] = v0;
            sv[4 * k + 1] = v1;
            sv[4 * k + 2] = v2;
            sv[4 * k + 3] = v3;
        }
        #pragma unroll
        for (int o = 16; o; o >>= 1) {
            mx   = fmaxf(mx, __shfl_xor_sync(0xFFFFFFFFu, mx, o));
            mn   = fminf(mn, __shfl_xor_sync(0xFFFFFFFFu, mn, o));
            stot +=          __shfl_xor_sync(0xFFFFFFFFu, stot, o);
        }

        // 2-cluster 1-D k-means. kL > kS => |s-kL|<=|s-kS| <=> s >= (kL+kS)/2
        // (midpoint tie -> large cluster, matches dl<=ds). Bitwise fixed point
        // => remaining reference iterations are no-ops -> exact early exit.
        float kL = mx, kS = mn;
        float lastCnt = 0.0f;
        #pragma unroll 1
        for (int it = 0; it < KMEAN; it++) {
            const float mid = 0.5f * (kL + kS);
            float s0 = 0.0f, s1 = 0.0f;
            int   ci = 0;
            #pragma unroll
            for (int k = 0; k < 64; k += 2) {
                const float a = sv[k], b = sv[k + 1];
                if (a >= mid) { s0 += a; ci++; }
                if (b >= mid) { s1 += b; ci++; }
            }
            float sumL = s0 + s1;
            #pragma unroll
            for (int o = 16; o; o >>= 1)
                sumL += __shfl_xor_sync(0xFFFFFFFFu, sumL, o);
            const float cntL = (float)__reduce_add_sync(0xFFFFFFFFu, ci);  // REDUX

            const float nkL = __fdividef(sumL, cntL);
            const float nkS = __fdividef(stot - sumL, (float)DENSE - cntL);
            lastCnt = cntL;
            const bool conv = (nkL == kL) && (nkS == kS);
            kL = nkL; kS = nkS;
            if (conv) break;
        }

        const bool keep = ((kL - kS) > 0.005f) && (lastCnt > 5.0f);
        if (lane == 0) {
            const float kf = keep ? 1.0f : 0.0f;
            out[2 * n]     = kL * kf;
            out[2 * n + 1] = kS * kf;
        }
    }
}

extern "C" void kernel_launch(void* const* d_in, const int* in_sizes, int n_in,
                              void* d_out, int out_size)
{
    const float* disp = (const float*)d_in[0];
    const float* fore = (const float*)d_in[1];
    const int*   cxs  = (const int*)  d_in[2];
    const int*   cys  = (const int*)  d_in[3];
    const int*   bxs  = (const int*)  d_in[4];
    const int*   bys  = (const int*)  d_in[5];
    float*       out  = (float*)d_out;

    rsbsp_fused<<<GRID_BLOCKS, 128>>>(disp, fore, cxs, cys, bxs, bys, out);
}

// round 6
// speedup vs baseline: 1.4345x; 1.4345x over previous
#include <cuda_runtime.h>
#include <cuda_bf16.h>

#define BCH   10
#define HH    320
#define WW    1024
#define PTS   500
#define DENSE 2000
#define KMEAN 10
#define NPTS  (BCH * PTS)
#define CHUNKS (DENSE / 4)      // 500 int4 chunks per point

// Window: by in [-7,7] (15 rows), bx in [-11,11] (23 cols), padded to 32 cols.
#define WROWS 15
#define WCOLS 23
#define HSLOTS (WROWS * 32)     // 480

// One warp per point; per-warp 480-slot histogram in smem.
__global__ __launch_bounds__(128, 6)
void rsbsp_kernel(const float* __restrict__ disp,
                  const float* __restrict__ fore,
                  const int*   __restrict__ cxs,
                  const int*   __restrict__ cys,
                  const int*   __restrict__ bxs,
                  const int*   __restrict__ bys,
                  float*       __restrict__ out)
{
    __shared__ int hist[4][HSLOTS];

    const int gwarp = (blockIdx.x * blockDim.x + threadIdx.x) >> 5;
    const int wid   = (threadIdx.x >> 5);        // warp within CTA (0..3)
    const int lane  = threadIdx.x & 31;
    if (gwarp >= NPTS) return;

    const int n    = gwarp;
    const int chan = n / PTS;
    const int cx   = cxs[n];
    const int cy   = cys[n];
    const float* dch = disp + (size_t)chan * (HH * WW);
    const float* fch = fore + (size_t)chan * (HH * WW);

    // ---- validRow: maxpool3x3(|sobel_x(forepred)|)(cy,cx) > 3.1 && disp > 0.007
    // Centers are >= 11 px from every border (zeroArea rows/cols never reached).
    float g = 0.0f;
    if (lane < 9) {
        const int dy = lane / 3 - 1;
        const int dx = lane % 3 - 1;
        const float* p = fch + (size_t)(cy + dy - 1) * WW + (cx + dx);
        const float a = p[1]  + 2.0f * p[WW + 1] + p[2 * WW + 1];
        const float b = p[-1] + 2.0f * p[WW - 1] + p[2 * WW - 1];
        g = fabsf(a - b);
    }
    #pragma unroll
    for (int o = 16; o; o >>= 1) g = fmaxf(g, __shfl_xor_sync(0xFFFFFFFFu, g, o));

    const int   base = (cy << 10) + cx;          // WW == 1024
    const float dC   = dch[base];

    if (!((g > 3.1f) && (dC > 0.007f))) {
        if (lane == 0) { out[2 * n] = 0.0f; out[2 * n + 1] = 0.0f; }
        return;
    }

    // ---- build sample-multiplicity histogram over the 15x23 window -------
    int* h = hist[wid];
    #pragma unroll
    for (int r = 0; r < WROWS; r++) h[lane + (r << 5)] = 0;
    __syncwarp();

    const int4* bx4p = (const int4*)(bxs + (size_t)n * DENSE);
    const int4* by4p = (const int4*)(bys + (size_t)n * DENSE);

    #pragma unroll 4
    for (int k = 0; k < 16; k++) {
        const int  c     = lane + (k << 5);
        const bool valid = (k < 15) || (c < CHUNKS);   // compile-time true k<15
        if (valid) {
            const int4 b4 = bx4p[c];
            const int4 y4 = by4p[c];
            // slot = (y+7)*32 + (x+11) = y*32 + x + 235
            atomicAdd(&h[(y4.x << 5) + b4.x + 235], 1);
            atomicAdd(&h[(y4.y << 5) + b4.y + 235], 1);
            atomicAdd(&h[(y4.z << 5) + b4.z + 235], 1);
            atomicAdd(&h[(y4.w << 5) + b4.w + 235], 1);
        }
    }
    __syncwarp();

    // ---- pull (val, prod, cnt) triples into registers; weighted stats -----
    float val [WROWS];
    float prod[WROWS];
    float cntf[WROWS];
    float mx = -1e30f, mn = 1e30f, stot = 0.0f;
    #pragma unroll
    for (int r = 0; r < WROWS; r++) {
        const int   cnt = h[lane + (r << 5)];
        const float v   = (lane < WCOLS)
                        ? dch[base + (r - 7) * WW + (lane - 11)]   // coalesced row read
                        : 0.0f;
        const float cf  = (float)cnt;
        val[r]  = v;
        cntf[r] = cf;
        prod[r] = v * cf;
        stot   += prod[r];
        if (cnt > 0) { mx = fmaxf(mx, v); mn = fminf(mn, v); }
    }
    #pragma unroll
    for (int o = 16; o; o >>= 1) {
        mx   = fmaxf(mx, __shfl_xor_sync(0xFFFFFFFFu, mx, o));
        mn   = fminf(mn, __shfl_xor_sync(0xFFFFFFFFu, mn, o));
        stot +=          __shfl_xor_sync(0xFFFFFFFFu, stot, o);
    }

    // ---- weighted 2-cluster 1-D k-means over <=345 unique values ----------
    // kL > kS => |s-kL|<=|s-kS| <=> s >= (kL+kS)/2 (midpoint tie -> large,
    // matching dl<=ds). Threshold acts on val only, so the weighted sums equal
    // the per-sample sums exactly (same partition). Bitwise fixed point =>
    // remaining reference iterations are no-ops -> exact early exit.
    float kL = mx, kS = mn;
    float lastCnt = 0.0f;
    #pragma unroll 1
    for (int it = 0; it < KMEAN; it++) {
        const float mid = 0.5f * (kL + kS);
        float sumL = 0.0f, cntL = 0.0f;
        #pragma unroll
        for (int r = 0; r < WROWS; r++) {
            if (val[r] >= mid) { sumL += prod[r]; cntL += cntf[r]; }
        }
        #pragma unroll
        for (int o = 16; o; o >>= 1) {
            sumL += __shfl_xor_sync(0xFFFFFFFFu, sumL, o);
            cntL += __shfl_xor_sync(0xFFFFFFFFu, cntL, o);
        }
        const float nkL = __fdividef(sumL, cntL);
        const float nkS = __fdividef(stot - sumL, (float)DENSE - cntL);
        lastCnt = cntL;
        const bool conv = (nkL == kL) && (nkS == kS);
        kL = nkL; kS = nkS;
        if (conv) break;
    }

    const bool keep = ((kL - kS) > 0.005f) && (lastCnt > 5.0f);
    if (lane == 0) {
        const float kf = keep ? 1.0f : 0.0f;
        out[2 * n]     = kL * kf;
        out[2 * n + 1] = kS * kf;
    }
}

extern "C" void kernel_launch(void* const* d_in, const int* in_sizes, int n_in,
                              void* d_out, int out_size)
{
    const float* disp = (const float*)d_in[0];
    const float* fore = (const float*)d_in[1];
    const int*   cxs  = (const int*)  d_in[2];
    const int*   cys  = (const int*)  d_in[3];
    const int*   bxs  = (const int*)  d_in[4];
    const int*   bys  = (const int*)  d_in[5];
    float*       out  = (float*)d_out;

    const int threads = 128;                       // 4 warps = 4 points / CTA
    const int blocks  = (NPTS * 32 + threads - 1) / threads;
    rsbsp_kernel<<<blocks, threads>>>(disp, fore, cxs, cys, bxs, bys, out);
}